// round 5
// baseline (speedup 1.0000x reference)
#include <cuda_runtime.h>
#include <cuda_bf16.h>
#include <math.h>

#define N_NODES 50000
#define N_EDGES 800000
#define DIN 512
#define DH 128
#define DOUTC 7
#define BN_EPS 1e-5f
#define SCAN_T 1024
#define BM 192

// ---------------- scratch (no cudaMalloc allowed) ----------------
__device__ int   g_cnt[N_NODES];
__device__ int   g_row[N_NODES];
__device__ int   g_cursor[N_NODES];
__device__ int   g_csr_src[N_EDGES];
__device__ float g_csr_w[N_EDGES];
__device__ float g_dinv[N_NODES];
__device__ float g_h1[N_NODES * DH];
__device__ float g_h2[N_NODES * DH];
__device__ float g_h3[N_NODES * DH];
__device__ float g_alpha1[DH];
__device__ float g_beta1[DH];
__device__ float g_alpha2[DH];
__device__ float g_beta2[DH];

// ---------------- CSR build ----------------
__global__ void k_zero() {
    int i = blockIdx.x * blockDim.x + threadIdx.x;
    if (i < N_NODES) g_cnt[i] = 0;
}

__global__ void k_hist(const int* __restrict__ ei) {
    int e = blockIdx.x * blockDim.x + threadIdx.x;
    if (e < N_EDGES) atomicAdd(&g_cnt[ei[N_EDGES + e]], 1);
}

__global__ void k_dinv() {
    int i = blockIdx.x * blockDim.x + threadIdx.x;
    if (i < N_NODES) g_dinv[i] = rsqrtf((float)(g_cnt[i] + 1));
}

__global__ __launch_bounds__(SCAN_T) void k_scan() {
    __shared__ int sums[SCAN_T];
    int t = threadIdx.x;
    const int CH = (N_NODES + SCAN_T - 1) / SCAN_T;
    int start = t * CH;
    int end = start + CH; if (end > N_NODES) end = N_NODES;
    int s = 0;
    for (int i = start; i < end; i++) s += g_cnt[i];
    sums[t] = s;
    __syncthreads();
    for (int off = 1; off < SCAN_T; off <<= 1) {
        int v = (t >= off) ? sums[t - off] : 0;
        __syncthreads();
        sums[t] += v;
        __syncthreads();
    }
    int run = (t == 0) ? 0 : sums[t - 1];
    for (int i = start; i < end; i++) {
        g_row[i] = run;
        g_cursor[i] = run;
        run += g_cnt[i];
    }
}

__global__ void k_fill(const int* __restrict__ ei) {
    int e = blockIdx.x * blockDim.x + threadIdx.x;
    if (e < N_EDGES) {
        int s = ei[e];
        int d = ei[N_EDGES + e];
        int p = atomicAdd(&g_cursor[d], 1);
        g_csr_src[p] = s;
        g_csr_w[p] = g_dinv[s] * g_dinv[d];
    }
}

// ---------------- BN affines ----------------
__global__ void k_bnparam2(const float* __restrict__ b1, const float* __restrict__ g1,
                           const float* __restrict__ be1, const float* __restrict__ rm1,
                           const float* __restrict__ rv1,
                           const float* __restrict__ b2, const float* __restrict__ g2,
                           const float* __restrict__ be2, const float* __restrict__ rm2,
                           const float* __restrict__ rv2) {
    int c = threadIdx.x;
    if (c < DH) {
        float a = g1[c] * rsqrtf(rv1[c] + BN_EPS);
        g_alpha1[c] = a;
        g_beta1[c]  = (b1[c] - rm1[c]) * a + be1[c];
    } else {
        int d = c - DH;
        float a = g2[d] * rsqrtf(rv2[d] + BN_EPS);
        g_alpha2[d] = a;
        g_beta2[d]  = (b2[d] - rm2[d]) * a + be2[d];
    }
}

// ---------------- bf16 MMA ----------------
__device__ __forceinline__ void mma_bf16(float* d, const unsigned* a, const unsigned* b) {
    asm volatile(
        "mma.sync.aligned.m16n8k16.row.col.f32.bf16.bf16.f32 "
        "{%0,%1,%2,%3}, {%4,%5,%6,%7}, {%8,%9}, {%0,%1,%2,%3};"
        : "+f"(d[0]), "+f"(d[1]), "+f"(d[2]), "+f"(d[3])
        : "r"(a[0]), "r"(a[1]), "r"(a[2]), "r"(a[3]), "r"(b[0]), "r"(b[1]));
}

// split fp32 pair -> (hi bf16x2, lo bf16x2)
__device__ __forceinline__ void split2(float x0, float x1, unsigned& hi, unsigned& lo) {
    __nv_bfloat162 h = __floats2bfloat162_rn(x0, x1);
    float h0 = __bfloat162float(__low2bfloat16(h));
    float h1 = __bfloat162float(__high2bfloat16(h));
    __nv_bfloat162 l = __floats2bfloat162_rn(x0 - h0, x1 - h1);
    hi = *(unsigned*)&h;
    lo = *(unsigned*)&l;
}

// ---------------- bf16x3 tensor GEMM: C[M,128] = A[M,K] * B[K,128] ----------------
// BM=192, BN=128, BK=16, 256 threads = 8 warps (4M x 2N), warp tile 48x64 (mt=3, nt=8).
// Fragment-major smem: A frags read via LDS.128, B frags via LDS.64, conflict-free.
// Double-buffered, LDG-early/STS-late pipeline.
__global__ __launch_bounds__(256) void gemm_bf16(
    const float* __restrict__ A, const float* __restrict__ B,
    float* __restrict__ C, int M, int K)
{
    // per stage: A = 12 m16-blocks * 32 lanes * 4 regs; B = 16 n8-blocks * 32 lanes * 2 regs
    __shared__ unsigned AsH[2][1536], AsL[2][1536];
    __shared__ unsigned BsH[2][1024], BsL[2][1024];

    int tid = threadIdx.x, wid = tid >> 5, lane = tid & 31;
    int wm = wid >> 1, wn = wid & 1, g = lane >> 2, t4 = lane & 3;
    int m0 = blockIdx.x * BM;

    float4 aR[3], bR[2];

    // --- LDG helpers (into regs) ---
    auto ldgA = [&](int t) {
#pragma unroll
        for (int i = 0; i < 3; i++) {
            int s = tid + i * 256;          // 768 slots: 192 rows x 4 k-quads
            int r = s >> 2, q = s & 3;
            int row = m0 + r;
            aR[i] = (row < M) ? *(const float4*)(A + (size_t)row * K + t * 16 + q * 4)
                              : make_float4(0.f, 0.f, 0.f, 0.f);
        }
    };
    auto ldgB = [&](int t) {
        int kp = tid >> 5, nq = tid & 31;   // kpair 0..7, n-quad 0..31
        const float* p = B + (size_t)(t * 16 + 2 * kp) * 128 + nq * 4;
        bR[0] = *(const float4*)p;
        bR[1] = *(const float4*)(p + 128);
    };

    // --- STS helpers (split + pack into fragment-major layout) ---
    auto stsA = [&](int st) {
#pragma unroll
        for (int i = 0; i < 3; i++) {
            int s = tid + i * 256;
            int r = s >> 2, q = s & 3;
            int m16 = r >> 4, rr = r & 15, gg = rr & 7, half = rr >> 3;
            float v[4] = { aR[i].x, aR[i].y, aR[i].z, aR[i].w };
#pragma unroll
            for (int j = 0; j < 2; j++) {
                int kp = 2 * q + j;
                int tt = kp & 3, rs = kp >> 2;
                unsigned hi, lo;
                split2(v[2 * j], v[2 * j + 1], hi, lo);
                int idx = ((m16 * 32) + 4 * gg + tt) * 4 + (half + 2 * rs);
                AsH[st][idx] = hi;
                AsL[st][idx] = lo;
            }
        }
    };
    auto stsB = [&](int st) {
        int kp = tid >> 5, nq = tid & 31;
        int tt = kp & 3, rs = kp >> 2;
        float r0[4] = { bR[0].x, bR[0].y, bR[0].z, bR[0].w };
        float r1[4] = { bR[1].x, bR[1].y, bR[1].z, bR[1].w };
#pragma unroll
        for (int j = 0; j < 4; j++) {
            int n = nq * 4 + j;
            int n8 = n >> 3, gg = n & 7;
            unsigned hi, lo;
            split2(r0[j], r1[j], hi, lo);
            int idx = ((n8 * 32) + 4 * gg + tt) * 2 + rs;
            BsH[st][idx] = hi;
            BsL[st][idx] = lo;
        }
    };

    float acc[3][8][4];
#pragma unroll
    for (int mt = 0; mt < 3; mt++)
#pragma unroll
        for (int nt = 0; nt < 8; nt++)
#pragma unroll
            for (int j = 0; j < 4; j++) acc[mt][nt][j] = 0.0f;

    ldgA(0); ldgB(0);
    stsA(0); stsB(0);
    __syncthreads();

    int T = K / 16;
    for (int t = 0; t < T; t++) {
        int cur = t & 1;
        if (t + 1 < T) { ldgA(t + 1); ldgB(t + 1); }

        unsigned ah[3][4], al[3][4];
#pragma unroll
        for (int mt = 0; mt < 3; mt++) {
            int base = ((wm * 3 + mt) * 32 + lane) * 4;
            *(uint4*)ah[mt] = *(const uint4*)&AsH[cur][base];
            *(uint4*)al[mt] = *(const uint4*)&AsL[cur][base];
        }
        unsigned bh[8][2];
#pragma unroll
        for (int nt = 0; nt < 8; nt++) {
            int base = (((wn * 8 + nt) * 32) + lane) * 2;
            *(uint2*)bh[nt] = *(const uint2*)&BsH[cur][base];
        }
        // pass 1: Ah*Bh
#pragma unroll
        for (int nt = 0; nt < 8; nt++)
#pragma unroll
            for (int mt = 0; mt < 3; mt++) mma_bf16(acc[mt][nt], ah[mt], bh[nt]);
        // pass 2: Al*Bh
#pragma unroll
        for (int nt = 0; nt < 8; nt++)
#pragma unroll
            for (int mt = 0; mt < 3; mt++) mma_bf16(acc[mt][nt], al[mt], bh[nt]);
        // pass 3: Ah*Bl (Bl transient)
#pragma unroll
        for (int nt = 0; nt < 8; nt++) {
            unsigned bl[2];
            int base = (((wn * 8 + nt) * 32) + lane) * 2;
            *(uint2*)bl = *(const uint2*)&BsL[cur][base];
#pragma unroll
            for (int mt = 0; mt < 3; mt++) mma_bf16(acc[mt][nt], ah[mt], bl);
        }

        if (t + 1 < T) { stsA((t + 1) & 1); stsB((t + 1) & 1); }
        __syncthreads();
    }

    // epilogue
#pragma unroll
    for (int mt = 0; mt < 3; mt++) {
        int r0 = m0 + wm * 48 + mt * 16 + g;
        int r1 = r0 + 8;
#pragma unroll
        for (int nt = 0; nt < 8; nt++) {
            int col = wn * 64 + nt * 8 + 2 * t4;
            if (r0 < M)
                *(float2*)(C + (size_t)r0 * 128 + col) = make_float2(acc[mt][nt][0], acc[mt][nt][1]);
            if (r1 < M)
                *(float2*)(C + (size_t)r1 * 128 + col) = make_float2(acc[mt][nt][2], acc[mt][nt][3]);
        }
    }
}

// ---------------- CSR aggregation: warp per node ----------------
// APPLY=1: write relu(alpha1*acc+beta1) (feeds GEMM2). APPLY=0: raw.
template<int APPLY>
__global__ __launch_bounds__(256) void k_agg(
    const float* __restrict__ h, float* __restrict__ out)
{
    int n = (blockIdx.x * blockDim.x + threadIdx.x) >> 5;
    int lane = threadIdx.x & 31;
    if (n >= N_NODES) return;

    float dv = g_dinv[n];
    float sl = dv * dv;
    float4 acc = ((const float4*)(h + (size_t)n * DH))[lane];
    acc.x *= sl; acc.y *= sl; acc.z *= sl; acc.w *= sl;

    int beg = g_row[n];
    int cnt = g_cnt[n];
    int e = beg;
    for (; e + 1 < beg + cnt; e += 2) {
        int s0 = g_csr_src[e];
        int s1 = g_csr_src[e + 1];
        float w0 = g_csr_w[e];
        float w1 = g_csr_w[e + 1];
        float4 v0 = ((const float4*)(h + (size_t)s0 * DH))[lane];
        float4 v1 = ((const float4*)(h + (size_t)s1 * DH))[lane];
        acc.x = fmaf(w0, v0.x, acc.x); acc.y = fmaf(w0, v0.y, acc.y);
        acc.z = fmaf(w0, v0.z, acc.z); acc.w = fmaf(w0, v0.w, acc.w);
        acc.x = fmaf(w1, v1.x, acc.x); acc.y = fmaf(w1, v1.y, acc.y);
        acc.z = fmaf(w1, v1.z, acc.z); acc.w = fmaf(w1, v1.w, acc.w);
    }
    if (e < beg + cnt) {
        int s0 = g_csr_src[e];
        float w0 = g_csr_w[e];
        float4 v0 = ((const float4*)(h + (size_t)s0 * DH))[lane];
        acc.x = fmaf(w0, v0.x, acc.x); acc.y = fmaf(w0, v0.y, acc.y);
        acc.z = fmaf(w0, v0.z, acc.z); acc.w = fmaf(w0, v0.w, acc.w);
    }
    if (APPLY) {
        float4 a  = ((const float4*)g_alpha1)[lane];
        float4 bt = ((const float4*)g_beta1)[lane];
        acc.x = fmaxf(fmaf(acc.x, a.x, bt.x), 0.f);
        acc.y = fmaxf(fmaf(acc.y, a.y, bt.y), 0.f);
        acc.z = fmaxf(fmaf(acc.z, a.z, bt.z), 0.f);
        acc.w = fmaxf(fmaf(acc.w, a.w, bt.w), 0.f);
    }
    ((float4*)(out + (size_t)n * DH))[lane] = acc;
}

// ---------------- final: relu(affine2(h)) @ Wfc + bfc, then log_softmax ----------------
__global__ __launch_bounds__(256) void k_fc_lsm(
    const float* __restrict__ h, const float* __restrict__ Wfc,
    const float* __restrict__ bfc, float* __restrict__ out)
{
    __shared__ float Ws[DH * DOUTC];
    __shared__ float bs[DOUTC];
    for (int i = threadIdx.x; i < DH * DOUTC; i += blockDim.x) Ws[i] = Wfc[i];
    if (threadIdx.x < DOUTC) bs[threadIdx.x] = bfc[threadIdx.x];
    __syncthreads();

    int row  = (blockIdx.x * blockDim.x + threadIdx.x) >> 5;
    int lane = threadIdx.x & 31;
    if (row >= N_NODES) return;

    const float* hr = h + (size_t)row * DH;
    float acc[DOUTC];
#pragma unroll
    for (int j = 0; j < DOUTC; j++) acc[j] = 0.0f;

#pragma unroll
    for (int i = 0; i < 4; i++) {
        int k = lane + i * 32;
        float hv = fmaxf(fmaf(hr[k], g_alpha2[k], g_beta2[k]), 0.f);
#pragma unroll
        for (int j = 0; j < DOUTC; j++)
            acc[j] = fmaf(hv, Ws[k * DOUTC + j], acc[j]);
    }
#pragma unroll
    for (int off = 16; off; off >>= 1)
#pragma unroll
        for (int j = 0; j < DOUTC; j++)
            acc[j] += __shfl_down_sync(0xffffffff, acc[j], off);

    if (lane == 0) {
        float m = -INFINITY;
#pragma unroll
        for (int j = 0; j < DOUTC; j++) { acc[j] += bs[j]; m = fmaxf(m, acc[j]); }
        float s = 0.0f;
#pragma unroll
        for (int j = 0; j < DOUTC; j++) s += expf(acc[j] - m);
        float lse = m + logf(s);
#pragma unroll
        for (int j = 0; j < DOUTC; j++)
            out[(size_t)row * DOUTC + j] = acc[j] - lse;
    }
}

// ---------------- launch ----------------
extern "C" void kernel_launch(void* const* d_in, const int* in_sizes, int n_in,
                              void* d_out, int out_size) {
    const float* x   = (const float*)d_in[0];
    const int*   ei  = (const int*)d_in[1];
    const float* W1  = (const float*)d_in[2];
    const float* b1  = (const float*)d_in[3];
    const float* g1  = (const float*)d_in[4];
    const float* be1 = (const float*)d_in[5];
    const float* rm1 = (const float*)d_in[6];
    const float* rv1 = (const float*)d_in[7];
    const float* W2  = (const float*)d_in[8];
    const float* b2  = (const float*)d_in[9];
    const float* g2  = (const float*)d_in[10];
    const float* be2 = (const float*)d_in[11];
    const float* rm2 = (const float*)d_in[12];
    const float* rv2 = (const float*)d_in[13];
    const float* Wfc = (const float*)d_in[14];
    const float* bfc = (const float*)d_in[15];
    float* out = (float*)d_out;

    float *p_h1, *p_h2, *p_h3;
    cudaGetSymbolAddress((void**)&p_h1, g_h1);
    cudaGetSymbolAddress((void**)&p_h2, g_h2);
    cudaGetSymbolAddress((void**)&p_h3, g_h3);

    const int GEMM_BLOCKS = (N_NODES + BM - 1) / BM;     // 261
    const int NODE_BLOCKS = (N_NODES + 255) / 256;
    const int EDGE_BLOCKS = (N_EDGES + 255) / 256;
    const int WARP_NODE_BLOCKS = (N_NODES + 7) / 8;

    // 0..2: histogram + dinv
    k_zero<<<NODE_BLOCKS, 256>>>();
    k_hist<<<EDGE_BLOCKS, 256>>>(ei);
    k_dinv<<<NODE_BLOCKS, 256>>>();

    // 3: GEMM1 (capture index 3 for ncu)
    gemm_bf16<<<GEMM_BLOCKS, 256>>>(x, W1, p_h1, N_NODES, DIN);

    // 4..6: CSR build + BN params (independent of GEMM1 output)
    k_scan<<<1, SCAN_T>>>();
    k_fill<<<EDGE_BLOCKS, 256>>>(ei);
    k_bnparam2<<<1, 256>>>(b1, g1, be1, rm1, rv1, b2, g2, be2, rm2, rv2);

    // 7: aggregate layer 1 + affine1 + relu
    k_agg<1><<<WARP_NODE_BLOCKS, 256>>>(p_h1, p_h2);

    // 8: GEMM2
    gemm_bf16<<<GEMM_BLOCKS, 256>>>(p_h2, W2, p_h1, N_NODES, DH);

    // 9: aggregate layer 2 (raw; fc applies affine2)
    k_agg<0><<<WARP_NODE_BLOCKS, 256>>>(p_h1, p_h3);

    // 10: FC + log_softmax
    k_fc_lsm<<<(N_NODES + 7) / 8, 256>>>(p_h3, Wfc, bfc, out);
}

// round 6
// speedup vs baseline: 1.1982x; 1.1982x over previous
#include <cuda_runtime.h>
#include <math.h>

#define N_NODES 50000
#define N_EDGES 800000
#define DIN 512
#define DH 128
#define DOUTC 7
#define BN_EPS 1e-5f
#define SCAN_T 1024

// ---------------- scratch (no cudaMalloc allowed) ----------------
__device__ int   g_cnt[N_NODES];
__device__ int   g_row[N_NODES];
__device__ int   g_cursor[N_NODES];
__device__ int   g_csr_src[N_EDGES];
__device__ float g_csr_w[N_EDGES];
__device__ float g_dinv[N_NODES];
__device__ float g_h1[N_NODES * DH];
__device__ float g_h2[N_NODES * DH];
__device__ float g_h3[N_NODES * DH];
__device__ float g_alpha1[DH];
__device__ float g_beta1[DH];
__device__ float g_alpha2[DH];
__device__ float g_beta2[DH];

// ---------------- CSR build ----------------
__global__ void k_zero() {
    int i = blockIdx.x * blockDim.x + threadIdx.x;
    if (i < N_NODES) g_cnt[i] = 0;
}

__global__ void k_hist(const int* __restrict__ ei) {
    int e = blockIdx.x * blockDim.x + threadIdx.x;
    if (e < N_EDGES) atomicAdd(&g_cnt[ei[N_EDGES + e]], 1);
}

__global__ void k_dinv() {
    int i = blockIdx.x * blockDim.x + threadIdx.x;
    if (i < N_NODES) g_dinv[i] = rsqrtf((float)(g_cnt[i] + 1));
}

__global__ __launch_bounds__(SCAN_T) void k_scan() {
    __shared__ int sums[SCAN_T];
    int t = threadIdx.x;
    const int CH = (N_NODES + SCAN_T - 1) / SCAN_T;
    int start = t * CH;
    int end = start + CH; if (end > N_NODES) end = N_NODES;
    int s = 0;
    for (int i = start; i < end; i++) s += g_cnt[i];
    sums[t] = s;
    __syncthreads();
    for (int off = 1; off < SCAN_T; off <<= 1) {
        int v = (t >= off) ? sums[t - off] : 0;
        __syncthreads();
        sums[t] += v;
        __syncthreads();
    }
    int run = (t == 0) ? 0 : sums[t - 1];
    for (int i = start; i < end; i++) {
        g_row[i] = run;
        g_cursor[i] = run;
        run += g_cnt[i];
    }
}

__global__ void k_fill(const int* __restrict__ ei) {
    int e = blockIdx.x * blockDim.x + threadIdx.x;
    if (e < N_EDGES) {
        int s = ei[e];
        int d = ei[N_EDGES + e];
        int p = atomicAdd(&g_cursor[d], 1);
        g_csr_src[p] = s;
        g_csr_w[p] = g_dinv[s] * g_dinv[d];
    }
}

// ---------------- BN affines ----------------
__global__ void k_bnparam2(const float* __restrict__ b1, const float* __restrict__ g1,
                           const float* __restrict__ be1, const float* __restrict__ rm1,
                           const float* __restrict__ rv1,
                           const float* __restrict__ b2, const float* __restrict__ g2,
                           const float* __restrict__ be2, const float* __restrict__ rm2,
                           const float* __restrict__ rv2) {
    int c = threadIdx.x;
    if (c < DH) {
        float a = g1[c] * rsqrtf(rv1[c] + BN_EPS);
        g_alpha1[c] = a;
        g_beta1[c]  = (b1[c] - rm1[c]) * a + be1[c];
    } else {
        int d = c - DH;
        float a = g2[d] * rsqrtf(rv2[d] + BN_EPS);
        g_alpha2[d] = a;
        g_beta2[d]  = (b2[d] - rm2[d]) * a + be2[d];
    }
}

// ---------------- tf32 helpers ----------------
__device__ __forceinline__ unsigned tf32_cvt(float f) {
    unsigned u;
    asm("cvt.rna.tf32.f32 %0, %1;" : "=r"(u) : "f"(f));
    return u;
}

__device__ __forceinline__ void mma_tf32(float* d, const unsigned* a, unsigned b0, unsigned b1) {
    asm volatile(
        "mma.sync.aligned.m16n8k8.row.col.f32.tf32.tf32.f32 "
        "{%0,%1,%2,%3}, {%4,%5,%6,%7}, {%8,%9}, {%0,%1,%2,%3};"
        : "+f"(d[0]), "+f"(d[1]), "+f"(d[2]), "+f"(d[3])
        : "r"(a[0]), "r"(a[1]), "r"(a[2]), "r"(a[3]), "r"(b0), "r"(b1));
}

// ---------------- tensor-core GEMM (proven R4 config): C[M,128] = A[M,K] * B[K,128] ----------------
// tf32x3 split precision. 256 threads = 8 warps (4M x 2N); warp tile 32x64. BK=16.
#define A_STR 20
#define B_STR 136
__global__ __launch_bounds__(256, 2) void gemm_tc(
    const float* __restrict__ A, const float* __restrict__ B,
    float* __restrict__ C, int M, int K)
{
    __shared__ float As[128 * A_STR];
    __shared__ float BsH[16 * B_STR];
    __shared__ float BsL[16 * B_STR];

    int tid = threadIdx.x, wid = tid >> 5, lane = tid & 31;
    int wm = wid >> 1, wn = wid & 1;
    int g = lane >> 2, t4 = lane & 3;
    int m0 = blockIdx.x * 128;

    float acc[2][8][4];
#pragma unroll
    for (int mt = 0; mt < 2; mt++)
#pragma unroll
        for (int nt = 0; nt < 8; nt++)
#pragma unroll
            for (int j = 0; j < 4; j++) acc[mt][nt][j] = 0.0f;

    for (int k0 = 0; k0 < K; k0 += 16) {
#pragma unroll
        for (int i = 0; i < 2; i++) {
            int slot = tid + i * 256;
            int r = slot >> 2, c = (slot & 3) * 4;
            int row = m0 + r;
            float4 a = make_float4(0.f, 0.f, 0.f, 0.f);
            if (row < M) a = *(const float4*)(A + (size_t)row * K + k0 + c);
            *(float4*)(&As[r * A_STR + c]) = a;
        }
#pragma unroll
        for (int i = 0; i < 2; i++) {
            int slot = tid + i * 256;
            int r = slot >> 5, c = (slot & 31) * 4;
            float4 b = *(const float4*)(B + (size_t)(k0 + r) * 128 + c);
            float4 bh, bl;
            unsigned u;
            u = tf32_cvt(b.x); bh.x = __uint_as_float(u); bl.x = __uint_as_float(tf32_cvt(b.x - __uint_as_float(u)));
            u = tf32_cvt(b.y); bh.y = __uint_as_float(u); bl.y = __uint_as_float(tf32_cvt(b.y - __uint_as_float(u)));
            u = tf32_cvt(b.z); bh.z = __uint_as_float(u); bl.z = __uint_as_float(tf32_cvt(b.z - __uint_as_float(u)));
            u = tf32_cvt(b.w); bh.w = __uint_as_float(u); bl.w = __uint_as_float(tf32_cvt(b.w - __uint_as_float(u)));
            *(float4*)(&BsH[r * B_STR + c]) = bh;
            *(float4*)(&BsL[r * B_STR + c]) = bl;
        }
        __syncthreads();

#pragma unroll
        for (int kk = 0; kk < 16; kk += 8) {
            unsigned ah[2][4], al[2][4];
#pragma unroll
            for (int mt = 0; mt < 2; mt++) {
                int mb = wm * 32 + mt * 16;
                float f0 = As[(mb + g)     * A_STR + kk + t4];
                float f1 = As[(mb + 8 + g) * A_STR + kk + t4];
                float f2 = As[(mb + g)     * A_STR + kk + 4 + t4];
                float f3 = As[(mb + 8 + g) * A_STR + kk + 4 + t4];
                ah[mt][0] = tf32_cvt(f0); al[mt][0] = tf32_cvt(f0 - __uint_as_float(ah[mt][0]));
                ah[mt][1] = tf32_cvt(f1); al[mt][1] = tf32_cvt(f1 - __uint_as_float(ah[mt][1]));
                ah[mt][2] = tf32_cvt(f2); al[mt][2] = tf32_cvt(f2 - __uint_as_float(ah[mt][2]));
                ah[mt][3] = tf32_cvt(f3); al[mt][3] = tf32_cvt(f3 - __uint_as_float(ah[mt][3]));
            }
#pragma unroll
            for (int nt = 0; nt < 8; nt++) {
                int n = wn * 64 + nt * 8 + g;
                unsigned b0h = __float_as_uint(BsH[(kk + t4)     * B_STR + n]);
                unsigned b1h = __float_as_uint(BsH[(kk + 4 + t4) * B_STR + n]);
                unsigned b0l = __float_as_uint(BsL[(kk + t4)     * B_STR + n]);
                unsigned b1l = __float_as_uint(BsL[(kk + 4 + t4) * B_STR + n]);
#pragma unroll
                for (int mt = 0; mt < 2; mt++) {
                    mma_tf32(acc[mt][nt], ah[mt], b0h, b1h);
                    mma_tf32(acc[mt][nt], ah[mt], b0l, b1l);
                    mma_tf32(acc[mt][nt], al[mt], b0h, b1h);
                }
            }
        }
        __syncthreads();
    }

#pragma unroll
    for (int mt = 0; mt < 2; mt++) {
        int row0 = m0 + wm * 32 + mt * 16 + g;
        int row1 = row0 + 8;
#pragma unroll
        for (int nt = 0; nt < 8; nt++) {
            int col = wn * 64 + nt * 8 + 2 * t4;
            if (row0 < M)
                *(float2*)(C + (size_t)row0 * 128 + col) = make_float2(acc[mt][nt][0], acc[mt][nt][1]);
            if (row1 < M)
                *(float2*)(C + (size_t)row1 * 128 + col) = make_float2(acc[mt][nt][2], acc[mt][nt][3]);
        }
    }
}

// ---------------- CSR aggregation: warp per node ----------------
// APPLY=1: write relu(alpha1*acc+beta1) (feeds GEMM2). APPLY=0: raw.
template<int APPLY>
__global__ __launch_bounds__(256) void k_agg(
    const float* __restrict__ h, float* __restrict__ out)
{
    int n = (blockIdx.x * blockDim.x + threadIdx.x) >> 5;
    int lane = threadIdx.x & 31;
    if (n >= N_NODES) return;

    float dv = g_dinv[n];
    float sl = dv * dv;
    float4 acc = ((const float4*)(h + (size_t)n * DH))[lane];
    acc.x *= sl; acc.y *= sl; acc.z *= sl; acc.w *= sl;

    int beg = g_row[n];
    int cnt = g_cnt[n];
    int e = beg;
    for (; e + 1 < beg + cnt; e += 2) {
        int s0 = g_csr_src[e];
        int s1 = g_csr_src[e + 1];
        float w0 = g_csr_w[e];
        float w1 = g_csr_w[e + 1];
        float4 v0 = ((const float4*)(h + (size_t)s0 * DH))[lane];
        float4 v1 = ((const float4*)(h + (size_t)s1 * DH))[lane];
        acc.x = fmaf(w0, v0.x, acc.x); acc.y = fmaf(w0, v0.y, acc.y);
        acc.z = fmaf(w0, v0.z, acc.z); acc.w = fmaf(w0, v0.w, acc.w);
        acc.x = fmaf(w1, v1.x, acc.x); acc.y = fmaf(w1, v1.y, acc.y);
        acc.z = fmaf(w1, v1.z, acc.z); acc.w = fmaf(w1, v1.w, acc.w);
    }
    if (e < beg + cnt) {
        int s0 = g_csr_src[e];
        float w0 = g_csr_w[e];
        float4 v0 = ((const float4*)(h + (size_t)s0 * DH))[lane];
        acc.x = fmaf(w0, v0.x, acc.x); acc.y = fmaf(w0, v0.y, acc.y);
        acc.z = fmaf(w0, v0.z, acc.z); acc.w = fmaf(w0, v0.w, acc.w);
    }
    if (APPLY) {
        float4 a  = ((const float4*)g_alpha1)[lane];
        float4 bt = ((const float4*)g_beta1)[lane];
        acc.x = fmaxf(fmaf(acc.x, a.x, bt.x), 0.f);
        acc.y = fmaxf(fmaf(acc.y, a.y, bt.y), 0.f);
        acc.z = fmaxf(fmaf(acc.z, a.z, bt.z), 0.f);
        acc.w = fmaxf(fmaf(acc.w, a.w, bt.w), 0.f);
    }
    ((float4*)(out + (size_t)n * DH))[lane] = acc;
}

// ---------------- final: relu(affine2(h)) @ Wfc + bfc, then log_softmax ----------------
__global__ __launch_bounds__(256) void k_fc_lsm(
    const float* __restrict__ h, const float* __restrict__ Wfc,
    const float* __restrict__ bfc, float* __restrict__ out)
{
    __shared__ float Ws[DH * DOUTC];
    __shared__ float bs[DOUTC];
    for (int i = threadIdx.x; i < DH * DOUTC; i += blockDim.x) Ws[i] = Wfc[i];
    if (threadIdx.x < DOUTC) bs[threadIdx.x] = bfc[threadIdx.x];
    __syncthreads();

    int row  = (blockIdx.x * blockDim.x + threadIdx.x) >> 5;
    int lane = threadIdx.x & 31;
    if (row >= N_NODES) return;

    const float* hr = h + (size_t)row * DH;
    float acc[DOUTC];
#pragma unroll
    for (int j = 0; j < DOUTC; j++) acc[j] = 0.0f;

#pragma unroll
    for (int i = 0; i < 4; i++) {
        int k = lane + i * 32;
        float hv = fmaxf(fmaf(hr[k], g_alpha2[k], g_beta2[k]), 0.f);
#pragma unroll
        for (int j = 0; j < DOUTC; j++)
            acc[j] = fmaf(hv, Ws[k * DOUTC + j], acc[j]);
    }
#pragma unroll
    for (int off = 16; off; off >>= 1)
#pragma unroll
        for (int j = 0; j < DOUTC; j++)
            acc[j] += __shfl_down_sync(0xffffffff, acc[j], off);

    if (lane == 0) {
        float m = -INFINITY;
#pragma unroll
        for (int j = 0; j < DOUTC; j++) { acc[j] += bs[j]; m = fmaxf(m, acc[j]); }
        float s = 0.0f;
#pragma unroll
        for (int j = 0; j < DOUTC; j++) s += expf(acc[j] - m);
        float lse = m + logf(s);
#pragma unroll
        for (int j = 0; j < DOUTC; j++)
            out[(size_t)row * DOUTC + j] = acc[j] - lse;
    }
}

// ---------------- launch ----------------
extern "C" void kernel_launch(void* const* d_in, const int* in_sizes, int n_in,
                              void* d_out, int out_size) {
    const float* x   = (const float*)d_in[0];
    const int*   ei  = (const int*)d_in[1];
    const float* W1  = (const float*)d_in[2];
    const float* b1  = (const float*)d_in[3];
    const float* g1  = (const float*)d_in[4];
    const float* be1 = (const float*)d_in[5];
    const float* rm1 = (const float*)d_in[6];
    const float* rv1 = (const float*)d_in[7];
    const float* W2  = (const float*)d_in[8];
    const float* b2  = (const float*)d_in[9];
    const float* g2  = (const float*)d_in[10];
    const float* be2 = (const float*)d_in[11];
    const float* rm2 = (const float*)d_in[12];
    const float* rv2 = (const float*)d_in[13];
    const float* Wfc = (const float*)d_in[14];
    const float* bfc = (const float*)d_in[15];
    float* out = (float*)d_out;

    float *p_h1, *p_h2, *p_h3;
    cudaGetSymbolAddress((void**)&p_h1, g_h1);
    cudaGetSymbolAddress((void**)&p_h2, g_h2);
    cudaGetSymbolAddress((void**)&p_h3, g_h3);

    // side stream + events, created once (host-side objects; no device memory)
    static cudaStream_t s2 = nullptr;
    static cudaEvent_t evFork = nullptr, evJoin = nullptr;
    if (s2 == nullptr) {
        cudaStreamCreateWithFlags(&s2, cudaStreamNonBlocking);
        cudaEventCreateWithFlags(&evFork, cudaEventDisableTiming);
        cudaEventCreateWithFlags(&evJoin, cudaEventDisableTiming);
    }

    const int GEMM_BLOCKS = (N_NODES + 127) / 128;
    const int NODE_BLOCKS = (N_NODES + 255) / 256;
    const int EDGE_BLOCKS = (N_EDGES + 255) / 256;
    const int WARP_NODE_BLOCKS = (N_NODES + 7) / 8;

    // fork: CSR-build chain on s2, GEMM1 on main stream (independent)
    cudaEventRecord(evFork, 0);
    cudaStreamWaitEvent(s2, evFork, 0);

    k_zero<<<NODE_BLOCKS, 256, 0, s2>>>();                              // 0
    k_hist<<<EDGE_BLOCKS, 256, 0, s2>>>(ei);                            // 1
    k_dinv<<<NODE_BLOCKS, 256, 0, s2>>>();                              // 2

    gemm_tc<<<GEMM_BLOCKS, 256>>>(x, W1, p_h1, N_NODES, DIN);           // 3 (profiled)

    k_scan<<<1, SCAN_T, 0, s2>>>();                                     // 4
    k_fill<<<EDGE_BLOCKS, 256, 0, s2>>>(ei);                            // 5
    k_bnparam2<<<1, 256, 0, s2>>>(b1, g1, be1, rm1, rv1,
                                  b2, g2, be2, rm2, rv2);               // 6
    cudaEventRecord(evJoin, s2);
    cudaStreamWaitEvent(0, evJoin, 0);

    // join: rest is serial on the main stream
    k_agg<1><<<WARP_NODE_BLOCKS, 256>>>(p_h1, p_h2);                    // 7
    gemm_tc<<<GEMM_BLOCKS, 256>>>(p_h2, W2, p_h1, N_NODES, DH);         // 8
    k_agg<0><<<WARP_NODE_BLOCKS, 256>>>(p_h1, p_h3);                    // 9
    k_fc_lsm<<<(N_NODES + 7) / 8, 256>>>(p_h3, Wfc, bfc, out);          // 10
}

// round 9
// speedup vs baseline: 1.3336x; 1.1130x over previous
#include <cuda_runtime.h>
#include <cuda_bf16.h>
#include <math.h>

#define N_NODES 50000
#define N_EDGES 800000
#define DIN 512
#define DH 128
#define DOUTC 7
#define BN_EPS 1e-5f
#define SCAN_T 1024

// ---------------- scratch (no cudaMalloc allowed) ----------------
__device__ int   g_cnt[N_NODES];
__device__ int   g_row[N_NODES];
__device__ int   g_cursor[N_NODES];
__device__ int   g_csr_src[N_EDGES];
__device__ float g_csr_w[N_EDGES];
__device__ float g_dinv[N_NODES];
__device__ __align__(16) float g_h1[N_NODES * DH];
__device__ __align__(16) float g_h2[N_NODES * DH];
__device__ __align__(16) float g_h3[N_NODES * DH];
__device__ float g_alpha1[DH];
__device__ float g_beta1[DH];
__device__ float g_alpha2[DH];
__device__ float g_beta2[DH];
// pre-transposed + bf16-split weights: [n][k] K-major
__device__ __align__(16) __nv_bfloat16 g_B1H[DH * DIN];
__device__ __align__(16) __nv_bfloat16 g_B1L[DH * DIN];
__device__ __align__(16) __nv_bfloat16 g_B2H[DH * DH];
__device__ __align__(16) __nv_bfloat16 g_B2L[DH * DH];

// ---------------- CSR build ----------------
__global__ void k_zero() {
    int i = blockIdx.x * blockDim.x + threadIdx.x;
    if (i < N_NODES) g_cnt[i] = 0;
}

__global__ void k_hist(const int* __restrict__ ei) {
    int e = blockIdx.x * blockDim.x + threadIdx.x;
    if (e < N_EDGES) atomicAdd(&g_cnt[ei[N_EDGES + e]], 1);
}

__global__ void k_dinv() {
    int i = blockIdx.x * blockDim.x + threadIdx.x;
    if (i < N_NODES) g_dinv[i] = rsqrtf((float)(g_cnt[i] + 1));
}

__global__ __launch_bounds__(SCAN_T) void k_scan() {
    __shared__ int sums[SCAN_T];
    int t = threadIdx.x;
    const int CH = (N_NODES + SCAN_T - 1) / SCAN_T;
    int start = t * CH;
    int end = start + CH; if (end > N_NODES) end = N_NODES;
    int s = 0;
    for (int i = start; i < end; i++) s += g_cnt[i];
    sums[t] = s;
    __syncthreads();
    for (int off = 1; off < SCAN_T; off <<= 1) {
        int v = (t >= off) ? sums[t - off] : 0;
        __syncthreads();
        sums[t] += v;
        __syncthreads();
    }
    int run = (t == 0) ? 0 : sums[t - 1];
    for (int i = start; i < end; i++) {
        g_row[i] = run;
        g_cursor[i] = run;
        run += g_cnt[i];
    }
}

__global__ void k_fill(const int* __restrict__ ei) {
    int e = blockIdx.x * blockDim.x + threadIdx.x;
    if (e < N_EDGES) {
        int s = ei[e];
        int d = ei[N_EDGES + e];
        int p = atomicAdd(&g_cursor[d], 1);
        g_csr_src[p] = s;
        g_csr_w[p] = g_dinv[s] * g_dinv[d];
    }
}

// ---------------- BN affines ----------------
__global__ void k_bnparam2(const float* __restrict__ b1, const float* __restrict__ g1,
                           const float* __restrict__ be1, const float* __restrict__ rm1,
                           const float* __restrict__ rv1,
                           const float* __restrict__ b2, const float* __restrict__ g2,
                           const float* __restrict__ be2, const float* __restrict__ rm2,
                           const float* __restrict__ rv2) {
    int c = threadIdx.x;
    if (c < DH) {
        float a = g1[c] * rsqrtf(rv1[c] + BN_EPS);
        g_alpha1[c] = a;
        g_beta1[c]  = (b1[c] - rm1[c]) * a + be1[c];
    } else {
        int d = c - DH;
        float a = g2[d] * rsqrtf(rv2[d] + BN_EPS);
        g_alpha2[d] = a;
        g_beta2[d]  = (b2[d] - rm2[d]) * a + be2[d];
    }
}

// ---------------- weight transpose + bf16 split: W[K,128] -> Bt[128][K] hi/lo ----------------
template<int K>
__global__ void k_prepB(const float* __restrict__ W,
                        __nv_bfloat16* __restrict__ BtH, __nv_bfloat16* __restrict__ BtL) {
    int idx = blockIdx.x * blockDim.x + threadIdx.x;
    if (idx < DH * K) {
        int n = idx / K, k = idx % K;
        float w = W[k * DH + n];
        __nv_bfloat16 h = __float2bfloat16(w);
        __nv_bfloat16 l = __float2bfloat16(w - __bfloat162float(h));
        BtH[idx] = h;
        BtL[idx] = l;
    }
}

// ---------------- bf16 MMA m16n8k16 ----------------
__device__ __forceinline__ void mma_bf16(float* d, const unsigned* a, const unsigned* b) {
    asm volatile(
        "mma.sync.aligned.m16n8k16.row.col.f32.bf16.bf16.f32 "
        "{%0,%1,%2,%3}, {%4,%5,%6,%7}, {%8,%9}, {%0,%1,%2,%3};"
        : "+f"(d[0]), "+f"(d[1]), "+f"(d[2]), "+f"(d[3])
        : "r"(a[0]), "r"(a[1]), "r"(a[2]), "r"(a[3]), "r"(b[0]), "r"(b[1]));
}

// pack (x even-k, y odd-k) fp32 -> bf16x2 hi + bf16x2 lo
__device__ __forceinline__ void packsplit(float x, float y, unsigned& hi, unsigned& lo) {
    __nv_bfloat162 h = __floats2bfloat162_rn(x, y);
    hi = *(unsigned*)&h;
    float hx = __bfloat162float(__low2bfloat16(h));
    float hy = __bfloat162float(__high2bfloat16(h));
    __nv_bfloat162 l = __floats2bfloat162_rn(x - hx, y - hy);
    lo = *(unsigned*)&l;
}

// ---------------- bf16x3 tensor GEMM: C[M,128] = A[M,K](fp32) * Bt^T ----------------
// BM=128, BN=128, BK=16. 256 threads = 8 warps (4M x 2N); warp tile 32x64.
// Packed k-pair fragments in row-major smem, stride 12 (conflict-free fragment loads).
// 3 passes: AhBh + AlBh + AhBl.
#define PSTR 12
__global__ __launch_bounds__(256, 2) void gemm_bf16p(
    const float* __restrict__ A,
    const __nv_bfloat16* __restrict__ BtH, const __nv_bfloat16* __restrict__ BtL,
    float* __restrict__ C, int M, int K)
{
    __shared__ unsigned AhP[128 * PSTR], AlP[128 * PSTR];
    __shared__ unsigned BhP[128 * PSTR], BlP[128 * PSTR];

    int tid = threadIdx.x, wid = tid >> 5, lane = tid & 31;
    int wm = wid >> 1, wn = wid & 1;
    int g = lane >> 2, t4 = lane & 3;
    int m0 = blockIdx.x * 128;

    float acc[2][8][4];
#pragma unroll
    for (int mt = 0; mt < 2; mt++)
#pragma unroll
        for (int nt = 0; nt < 8; nt++)
#pragma unroll
            for (int j = 0; j < 4; j++) acc[mt][nt][j] = 0.0f;

    for (int k0 = 0; k0 < K; k0 += 16) {
        // A tile: 128 rows x 16 k fp32 -> packed bf16 pairs hi/lo
#pragma unroll
        for (int i = 0; i < 2; i++) {
            int slot = tid + i * 256;          // 512 float4 slots
            int r = slot >> 2, c = slot & 3;   // c = k-quad
            int row = m0 + r; if (row >= M) row = M - 1;
            float4 a = *(const float4*)(A + (size_t)row * K + k0 + c * 4);
            unsigned h0, l0, h1, l1;
            packsplit(a.x, a.y, h0, l0);
            packsplit(a.z, a.w, h1, l1);
            int base = r * PSTR + c * 2;
            *(uint2*)&AhP[base] = make_uint2(h0, h1);
            *(uint2*)&AlP[base] = make_uint2(l0, l1);
        }
        // B tile: 128 n x 16 k bf16 (pre-split) -> packed pairs are just u32 views
        {
            int n = tid >> 1, q = tid & 1;     // q: kp 0-3 or 4-7
            const __nv_bfloat16* ph = BtH + (size_t)n * K + k0 + q * 8;
            const __nv_bfloat16* pl = BtL + (size_t)n * K + k0 + q * 8;
            *(uint4*)&BhP[n * PSTR + q * 4] = *(const uint4*)ph;
            *(uint4*)&BlP[n * PSTR + q * 4] = *(const uint4*)pl;
        }
        __syncthreads();

        // fragments
        unsigned ah[2][4], al[2][4];
#pragma unroll
        for (int mt = 0; mt < 2; mt++) {
            int mb = wm * 32 + mt * 16;
            ah[mt][0] = AhP[(mb + g)     * PSTR + t4];
            ah[mt][1] = AhP[(mb + 8 + g) * PSTR + t4];
            ah[mt][2] = AhP[(mb + g)     * PSTR + 4 + t4];
            ah[mt][3] = AhP[(mb + 8 + g) * PSTR + 4 + t4];
            al[mt][0] = AlP[(mb + g)     * PSTR + t4];
            al[mt][1] = AlP[(mb + 8 + g) * PSTR + t4];
            al[mt][2] = AlP[(mb + g)     * PSTR + 4 + t4];
            al[mt][3] = AlP[(mb + 8 + g) * PSTR + 4 + t4];
        }
        unsigned bh[8][2], bl[8][2];
#pragma unroll
        for (int nt = 0; nt < 8; nt++) {
            int n = wn * 64 + nt * 8 + g;
            bh[nt][0] = BhP[n * PSTR + t4];
            bh[nt][1] = BhP[n * PSTR + 4 + t4];
            bl[nt][0] = BlP[n * PSTR + t4];
            bl[nt][1] = BlP[n * PSTR + 4 + t4];
        }
        // pass 1: Ah*Bh
#pragma unroll
        for (int nt = 0; nt < 8; nt++)
#pragma unroll
            for (int mt = 0; mt < 2; mt++) mma_bf16(acc[mt][nt], ah[mt], bh[nt]);
        // pass 2: Al*Bh
#pragma unroll
        for (int nt = 0; nt < 8; nt++)
#pragma unroll
            for (int mt = 0; mt < 2; mt++) mma_bf16(acc[mt][nt], al[mt], bh[nt]);
        // pass 3: Ah*Bl
#pragma unroll
        for (int nt = 0; nt < 8; nt++)
#pragma unroll
            for (int mt = 0; mt < 2; mt++) mma_bf16(acc[mt][nt], ah[mt], bl[nt]);
        __syncthreads();
    }

    // epilogue
#pragma unroll
    for (int mt = 0; mt < 2; mt++) {
        int row0 = m0 + wm * 32 + mt * 16 + g;
        int row1 = row0 + 8;
#pragma unroll
        for (int nt = 0; nt < 8; nt++) {
            int col = wn * 64 + nt * 8 + 2 * t4;
            if (row0 < M)
                *(float2*)(C + (size_t)row0 * 128 + col) = make_float2(acc[mt][nt][0], acc[mt][nt][1]);
            if (row1 < M)
                *(float2*)(C + (size_t)row1 * 128 + col) = make_float2(acc[mt][nt][2], acc[mt][nt][3]);
        }
    }
}

// ---------------- CSR aggregation: warp per node ----------------
template<int APPLY>
__global__ __launch_bounds__(256) void k_agg(
    const float* __restrict__ h, float* __restrict__ out)
{
    int n = (blockIdx.x * blockDim.x + threadIdx.x) >> 5;
    int lane = threadIdx.x & 31;
    if (n >= N_NODES) return;

    float dv = g_dinv[n];
    float sl = dv * dv;
    float4 acc = ((const float4*)(h + (size_t)n * DH))[lane];
    acc.x *= sl; acc.y *= sl; acc.z *= sl; acc.w *= sl;

    int beg = g_row[n];
    int cnt = g_cnt[n];
    int e = beg;
    for (; e + 1 < beg + cnt; e += 2) {
        int s0 = g_csr_src[e];
        int s1 = g_csr_src[e + 1];
        float w0 = g_csr_w[e];
        float w1 = g_csr_w[e + 1];
        float4 v0 = ((const float4*)(h + (size_t)s0 * DH))[lane];
        float4 v1 = ((const float4*)(h + (size_t)s1 * DH))[lane];
        acc.x = fmaf(w0, v0.x, acc.x); acc.y = fmaf(w0, v0.y, acc.y);
        acc.z = fmaf(w0, v0.z, acc.z); acc.w = fmaf(w0, v0.w, acc.w);
        acc.x = fmaf(w1, v1.x, acc.x); acc.y = fmaf(w1, v1.y, acc.y);
        acc.z = fmaf(w1, v1.z, acc.z); acc.w = fmaf(w1, v1.w, acc.w);
    }
    if (e < beg + cnt) {
        int s0 = g_csr_src[e];
        float w0 = g_csr_w[e];
        float4 v0 = ((const float4*)(h + (size_t)s0 * DH))[lane];
        acc.x = fmaf(w0, v0.x, acc.x); acc.y = fmaf(w0, v0.y, acc.y);
        acc.z = fmaf(w0, v0.z, acc.z); acc.w = fmaf(w0, v0.w, acc.w);
    }
    if (APPLY) {
        float4 a  = ((const float4*)g_alpha1)[lane];
        float4 bt = ((const float4*)g_beta1)[lane];
        acc.x = fmaxf(fmaf(acc.x, a.x, bt.x), 0.f);
        acc.y = fmaxf(fmaf(acc.y, a.y, bt.y), 0.f);
        acc.z = fmaxf(fmaf(acc.z, a.z, bt.z), 0.f);
        acc.w = fmaxf(fmaf(acc.w, a.w, bt.w), 0.f);
    }
    ((float4*)(out + (size_t)n * DH))[lane] = acc;
}

// ---------------- final: relu(affine2(h)) @ Wfc + bfc, then log_softmax ----------------
__global__ __launch_bounds__(256) void k_fc_lsm(
    const float* __restrict__ h, const float* __restrict__ Wfc,
    const float* __restrict__ bfc, float* __restrict__ out)
{
    __shared__ float Ws[DH * DOUTC];
    __shared__ float bs[DOUTC];
    for (int i = threadIdx.x; i < DH * DOUTC; i += blockDim.x) Ws[i] = Wfc[i];
    if (threadIdx.x < DOUTC) bs[threadIdx.x] = bfc[threadIdx.x];
    __syncthreads();

    int row  = (blockIdx.x * blockDim.x + threadIdx.x) >> 5;
    int lane = threadIdx.x & 31;
    if (row >= N_NODES) return;

    const float* hr = h + (size_t)row * DH;
    float acc[DOUTC];
#pragma unroll
    for (int j = 0; j < DOUTC; j++) acc[j] = 0.0f;

#pragma unroll
    for (int i = 0; i < 4; i++) {
        int k = lane + i * 32;
        float hv = fmaxf(fmaf(hr[k], g_alpha2[k], g_beta2[k]), 0.f);
#pragma unroll
        for (int j = 0; j < DOUTC; j++)
            acc[j] = fmaf(hv, Ws[k * DOUTC + j], acc[j]);
    }
#pragma unroll
    for (int off = 16; off; off >>= 1)
#pragma unroll
        for (int j = 0; j < DOUTC; j++)
            acc[j] += __shfl_down_sync(0xffffffff, acc[j], off);

    if (lane == 0) {
        float m = -INFINITY;
#pragma unroll
        for (int j = 0; j < DOUTC; j++) { acc[j] += bs[j]; m = fmaxf(m, acc[j]); }
        float s = 0.0f;
#pragma unroll
        for (int j = 0; j < DOUTC; j++) s += expf(acc[j] - m);
        float lse = m + logf(s);
#pragma unroll
        for (int j = 0; j < DOUTC; j++)
            out[(size_t)row * DOUTC + j] = acc[j] - lse;
    }
}

// ---------------- launch ----------------
extern "C" void kernel_launch(void* const* d_in, const int* in_sizes, int n_in,
                              void* d_out, int out_size) {
    const float* x   = (const float*)d_in[0];
    const int*   ei  = (const int*)d_in[1];
    const float* W1  = (const float*)d_in[2];
    const float* b1  = (const float*)d_in[3];
    const float* g1  = (const float*)d_in[4];
    const float* be1 = (const float*)d_in[5];
    const float* rm1 = (const float*)d_in[6];
    const float* rv1 = (const float*)d_in[7];
    const float* W2  = (const float*)d_in[8];
    const float* b2  = (const float*)d_in[9];
    const float* g2  = (const float*)d_in[10];
    const float* be2 = (const float*)d_in[11];
    const float* rm2 = (const float*)d_in[12];
    const float* rv2 = (const float*)d_in[13];
    const float* Wfc = (const float*)d_in[14];
    const float* bfc = (const float*)d_in[15];
    float* out = (float*)d_out;

    float *p_h1, *p_h2, *p_h3;
    __nv_bfloat16 *p_B1H, *p_B1L, *p_B2H, *p_B2L;
    cudaGetSymbolAddress((void**)&p_h1, g_h1);
    cudaGetSymbolAddress((void**)&p_h2, g_h2);
    cudaGetSymbolAddress((void**)&p_h3, g_h3);
    cudaGetSymbolAddress((void**)&p_B1H, g_B1H);
    cudaGetSymbolAddress((void**)&p_B1L, g_B1L);
    cudaGetSymbolAddress((void**)&p_B2H, g_B2H);
    cudaGetSymbolAddress((void**)&p_B2L, g_B2L);

    static cudaStream_t s2 = nullptr;
    static cudaEvent_t evFork = nullptr, evJoin = nullptr;
    if (s2 == nullptr) {
        cudaStreamCreateWithFlags(&s2, cudaStreamNonBlocking);
        cudaEventCreateWithFlags(&evFork, cudaEventDisableTiming);
        cudaEventCreateWithFlags(&evJoin, cudaEventDisableTiming);
    }

    const int GEMM_BLOCKS = (N_NODES + 127) / 128;
    const int NODE_BLOCKS = (N_NODES + 255) / 256;
    const int EDGE_BLOCKS = (N_EDGES + 255) / 256;
    const int WARP_NODE_BLOCKS = (N_NODES + 7) / 8;

    // fork: CSR-build chain on s2 (independent of GEMM path)
    cudaEventRecord(evFork, 0);
    cudaStreamWaitEvent(s2, evFork, 0);

    k_prepB<DIN><<<(DH * DIN + 255) / 256, 256>>>(W1, p_B1H, p_B1L);     // 0 (main)
    k_zero<<<NODE_BLOCKS, 256, 0, s2>>>();                               // 1
    k_hist<<<EDGE_BLOCKS, 256, 0, s2>>>(ei);                             // 2
    gemm_bf16p<<<GEMM_BLOCKS, 256>>>(x, p_B1H, p_B1L, p_h1,
                                     N_NODES, DIN);                      // 3 (profiled)
    k_dinv<<<NODE_BLOCKS, 256, 0, s2>>>();                               // 4
    k_scan<<<1, SCAN_T, 0, s2>>>();                                      // 5
    k_fill<<<EDGE_BLOCKS, 256, 0, s2>>>(ei);                             // 6
    k_bnparam2<<<1, 256, 0, s2>>>(b1, g1, be1, rm1, rv1,
                                  b2, g2, be2, rm2, rv2);                // 7
    cudaEventRecord(evJoin, s2);
    cudaStreamWaitEvent(0, evJoin, 0);

    k_prepB<DH><<<(DH * DH + 255) / 256, 256>>>(W2, p_B2H, p_B2L);       // 8
    k_agg<1><<<WARP_NODE_BLOCKS, 256>>>(p_h1, p_h2);                     // 9
    gemm_bf16p<<<GEMM_BLOCKS, 256>>>(p_h2, p_B2H, p_B2L, p_h1,
                                     N_NODES, DH);                       // 10
    k_agg<0><<<WARP_NODE_BLOCKS, 256>>>(p_h1, p_h3);                     // 11
    k_fc_lsm<<<(N_NODES + 7) / 8, 256>>>(p_h3, Wfc, bfc, out);           // 12
}

// round 10
// speedup vs baseline: 1.4016x; 1.0509x over previous
#include <cuda_runtime.h>
#include <cuda_bf16.h>
#include <math.h>
#include <stdint.h>

#define N_NODES 50000
#define N_EDGES 800000
#define DIN 512
#define DH 128
#define DOUTC 7
#define BN_EPS 1e-5f
#define SCAN_T 1024

// ---------------- scratch (no cudaMalloc allowed) ----------------
__device__ int   g_cnt[N_NODES];
__device__ int   g_row[N_NODES];
__device__ int   g_cursor[N_NODES];
__device__ int   g_csr_src[N_EDGES];
__device__ float g_csr_w[N_EDGES];
__device__ float g_dinv[N_NODES];
__device__ __align__(16) float g_h1[N_NODES * DH];
__device__ __align__(16) float g_h2[N_NODES * DH];
__device__ __align__(16) float g_h3[N_NODES * DH];
__device__ float g_alpha1[DH];
__device__ float g_beta1[DH];
__device__ float g_alpha2[DH];
__device__ float g_beta2[DH];
// pre-transposed + bf16-split weights: [n][k] K-major
__device__ __align__(16) __nv_bfloat16 g_B1H[DH * DIN];
__device__ __align__(16) __nv_bfloat16 g_B1L[DH * DIN];
__device__ __align__(16) __nv_bfloat16 g_B2H[DH * DH];
__device__ __align__(16) __nv_bfloat16 g_B2L[DH * DH];

// ---------------- CSR build ----------------
__global__ void k_zero() {
    int i = blockIdx.x * blockDim.x + threadIdx.x;
    if (i < N_NODES) g_cnt[i] = 0;
}

__global__ void k_hist(const int* __restrict__ ei) {
    int e = blockIdx.x * blockDim.x + threadIdx.x;
    if (e < N_EDGES) atomicAdd(&g_cnt[ei[N_EDGES + e]], 1);
}

__global__ void k_dinv() {
    int i = blockIdx.x * blockDim.x + threadIdx.x;
    if (i < N_NODES) g_dinv[i] = rsqrtf((float)(g_cnt[i] + 1));
}

__global__ __launch_bounds__(SCAN_T) void k_scan() {
    __shared__ int sums[SCAN_T];
    int t = threadIdx.x;
    const int CH = (N_NODES + SCAN_T - 1) / SCAN_T;
    int start = t * CH;
    int end = start + CH; if (end > N_NODES) end = N_NODES;
    int s = 0;
    for (int i = start; i < end; i++) s += g_cnt[i];
    sums[t] = s;
    __syncthreads();
    for (int off = 1; off < SCAN_T; off <<= 1) {
        int v = (t >= off) ? sums[t - off] : 0;
        __syncthreads();
        sums[t] += v;
        __syncthreads();
    }
    int run = (t == 0) ? 0 : sums[t - 1];
    for (int i = start; i < end; i++) {
        g_row[i] = run;
        g_cursor[i] = run;
        run += g_cnt[i];
    }
}

__global__ void k_fill(const int* __restrict__ ei) {
    int e = blockIdx.x * blockDim.x + threadIdx.x;
    if (e < N_EDGES) {
        int s = ei[e];
        int d = ei[N_EDGES + e];
        int p = atomicAdd(&g_cursor[d], 1);
        g_csr_src[p] = s;
        g_csr_w[p] = g_dinv[s] * g_dinv[d];
    }
}

// ---------------- BN affines ----------------
__global__ void k_bnparam2(const float* __restrict__ b1, const float* __restrict__ g1,
                           const float* __restrict__ be1, const float* __restrict__ rm1,
                           const float* __restrict__ rv1,
                           const float* __restrict__ b2, const float* __restrict__ g2,
                           const float* __restrict__ be2, const float* __restrict__ rm2,
                           const float* __restrict__ rv2) {
    int c = threadIdx.x;
    if (c < DH) {
        float a = g1[c] * rsqrtf(rv1[c] + BN_EPS);
        g_alpha1[c] = a;
        g_beta1[c]  = (b1[c] - rm1[c]) * a + be1[c];
    } else {
        int d = c - DH;
        float a = g2[d] * rsqrtf(rv2[d] + BN_EPS);
        g_alpha2[d] = a;
        g_beta2[d]  = (b2[d] - rm2[d]) * a + be2[d];
    }
}

// ---------------- weight transpose + bf16 split ----------------
template<int K>
__global__ void k_prepB(const float* __restrict__ W,
                        __nv_bfloat16* __restrict__ BtH, __nv_bfloat16* __restrict__ BtL) {
    int idx = blockIdx.x * blockDim.x + threadIdx.x;
    if (idx < DH * K) {
        int n = idx / K, k = idx % K;
        float w = W[k * DH + n];
        __nv_bfloat16 h = __float2bfloat16(w);
        __nv_bfloat16 l = __float2bfloat16(w - __bfloat162float(h));
        BtH[idx] = h;
        BtL[idx] = l;
    }
}

// ---------------- bf16 MMA m16n8k16 ----------------
__device__ __forceinline__ void mma_bf16(float* d, const unsigned* a, const unsigned* b) {
    asm volatile(
        "mma.sync.aligned.m16n8k16.row.col.f32.bf16.bf16.f32 "
        "{%0,%1,%2,%3}, {%4,%5,%6,%7}, {%8,%9}, {%0,%1,%2,%3};"
        : "+f"(d[0]), "+f"(d[1]), "+f"(d[2]), "+f"(d[3])
        : "r"(a[0]), "r"(a[1]), "r"(a[2]), "r"(a[3]), "r"(b[0]), "r"(b[1]));
}

__device__ __forceinline__ void packsplit(float x, float y, unsigned& hi, unsigned& lo) {
    __nv_bfloat162 h = __floats2bfloat162_rn(x, y);
    hi = *(unsigned*)&h;
    float hx = __bfloat162float(__low2bfloat16(h));
    float hy = __bfloat162float(__high2bfloat16(h));
    __nv_bfloat162 l = __floats2bfloat162_rn(x - hx, y - hy);
    lo = *(unsigned*)&l;
}

__device__ __forceinline__ void cpa16(uint32_t dst, const void* src) {
    asm volatile("cp.async.cg.shared.global [%0], [%1], 16;" :: "r"(dst), "l"(src) : "memory");
}
__device__ __forceinline__ void cpa_commit() {
    asm volatile("cp.async.commit_group;" ::: "memory");
}

// ---------------- bf16x3 GEMM, cp.async double-buffered ----------------
// BM=128, BN=128, BK=16. 8 warps (4M x 2N), warp tile 32x64.
// A raw fp32 in smem (stride 24 words, conflict-free LDS.64 fragment loads),
// split to bf16 hi/lo at fragment-load time. B pre-split bf16, stride-12 layout.
#define ASTR 24
#define BSTR 12
__global__ __launch_bounds__(256, 2) void gemm_cp(
    const float* __restrict__ A,
    const __nv_bfloat16* __restrict__ BtH, const __nv_bfloat16* __restrict__ BtL,
    float* __restrict__ C, int M, int K)
{
    __shared__ float    Afp[2][128 * ASTR];     // 2 x 12 KB
    __shared__ unsigned Bh[2][128 * BSTR];      // 2 x 6 KB
    __shared__ unsigned Bl[2][128 * BSTR];      // 2 x 6 KB

    int tid = threadIdx.x, wid = tid >> 5, lane = tid & 31;
    int wm = wid >> 1, wn = wid & 1;
    int g = lane >> 2, t4 = lane & 3;
    int m0 = blockIdx.x * 128;

    uint32_t aBase  = (uint32_t)__cvta_generic_to_shared(&Afp[0][0]);
    uint32_t bhBase = (uint32_t)__cvta_generic_to_shared(&Bh[0][0]);
    uint32_t blBase = (uint32_t)__cvta_generic_to_shared(&Bl[0][0]);

    // addresses for this thread's async copies
    int rA = tid >> 2, cA = tid & 3;            // A: 2 chunks (slot, slot+256)
    int rA2 = (tid + 256) >> 2, cA2 = (tid + 256) & 3;
    int rowA  = m0 + rA;  if (rowA  >= M) rowA  = M - 1;
    int rowA2 = m0 + rA2; if (rowA2 >= M) rowA2 = M - 1;
    int nB = tid >> 1, qB = tid & 1;

    auto issue = [&](int t, int st) {
        int k0 = t * 16;
        cpa16(aBase + (uint32_t)(st * 128 * ASTR + rA * ASTR + cA * 4) * 4,
              A + (size_t)rowA * K + k0 + cA * 4);
        cpa16(aBase + (uint32_t)(st * 128 * ASTR + rA2 * ASTR + cA2 * 4) * 4,
              A + (size_t)rowA2 * K + k0 + cA2 * 4);
        cpa16(bhBase + (uint32_t)(st * 128 * BSTR + nB * BSTR + qB * 4) * 4,
              BtH + (size_t)nB * K + k0 + qB * 8);
        cpa16(blBase + (uint32_t)(st * 128 * BSTR + nB * BSTR + qB * 4) * 4,
              BtL + (size_t)nB * K + k0 + qB * 8);
        cpa_commit();
    };

    float acc[2][8][4];
#pragma unroll
    for (int mt = 0; mt < 2; mt++)
#pragma unroll
        for (int nt = 0; nt < 8; nt++)
#pragma unroll
            for (int j = 0; j < 4; j++) acc[mt][nt][j] = 0.0f;

    int T = K / 16;
    issue(0, 0);

    for (int t = 0; t < T; t++) {
        int cur = t & 1;
        if (t + 1 < T) {
            issue(t + 1, cur ^ 1);
            asm volatile("cp.async.wait_group 1;" ::: "memory");
        } else {
            asm volatile("cp.async.wait_group 0;" ::: "memory");
        }
        __syncthreads();

        const float* Ab = &Afp[cur][0];
        const unsigned* Bhb = &Bh[cur][0];
        const unsigned* Blb = &Bl[cur][0];

        // A fragments: load fp32 pairs, split to bf16 hi/lo
        unsigned ah[2][4], al[2][4];
#pragma unroll
        for (int mt = 0; mt < 2; mt++) {
            int mb = wm * 32 + mt * 16;
            float2 p0 = *(const float2*)&Ab[(mb + g)     * ASTR + 2 * t4];
            float2 p1 = *(const float2*)&Ab[(mb + 8 + g) * ASTR + 2 * t4];
            float2 p2 = *(const float2*)&Ab[(mb + g)     * ASTR + 8 + 2 * t4];
            float2 p3 = *(const float2*)&Ab[(mb + 8 + g) * ASTR + 8 + 2 * t4];
            packsplit(p0.x, p0.y, ah[mt][0], al[mt][0]);
            packsplit(p1.x, p1.y, ah[mt][1], al[mt][1]);
            packsplit(p2.x, p2.y, ah[mt][2], al[mt][2]);
            packsplit(p3.x, p3.y, ah[mt][3], al[mt][3]);
        }
        unsigned bh[8][2];
#pragma unroll
        for (int nt = 0; nt < 8; nt++) {
            int n = wn * 64 + nt * 8 + g;
            bh[nt][0] = Bhb[n * BSTR + t4];
            bh[nt][1] = Bhb[n * BSTR + 4 + t4];
        }
        // pass 1: Ah*Bh
#pragma unroll
        for (int nt = 0; nt < 8; nt++)
#pragma unroll
            for (int mt = 0; mt < 2; mt++) mma_bf16(acc[mt][nt], ah[mt], bh[nt]);
        // pass 2: Al*Bh
#pragma unroll
        for (int nt = 0; nt < 8; nt++)
#pragma unroll
            for (int mt = 0; mt < 2; mt++) mma_bf16(acc[mt][nt], al[mt], bh[nt]);
        // pass 3: Ah*Bl (transient)
#pragma unroll
        for (int nt = 0; nt < 8; nt++) {
            unsigned bl[2];
            int n = wn * 64 + nt * 8 + g;
            bl[0] = Blb[n * BSTR + t4];
            bl[1] = Blb[n * BSTR + 4 + t4];
#pragma unroll
            for (int mt = 0; mt < 2; mt++) mma_bf16(acc[mt][nt], ah[mt], bl);
        }
        __syncthreads();
    }

    // epilogue
#pragma unroll
    for (int mt = 0; mt < 2; mt++) {
        int row0 = m0 + wm * 32 + mt * 16 + g;
        int row1 = row0 + 8;
#pragma unroll
        for (int nt = 0; nt < 8; nt++) {
            int col = wn * 64 + nt * 8 + 2 * t4;
            if (row0 < M)
                *(float2*)(C + (size_t)row0 * 128 + col) = make_float2(acc[mt][nt][0], acc[mt][nt][1]);
            if (row1 < M)
                *(float2*)(C + (size_t)row1 * 128 + col) = make_float2(acc[mt][nt][2], acc[mt][nt][3]);
        }
    }
}

// ---------------- CSR aggregation: warp per node ----------------
template<int APPLY>
__global__ __launch_bounds__(256) void k_agg(
    const float* __restrict__ h, float* __restrict__ out)
{
    int n = (blockIdx.x * blockDim.x + threadIdx.x) >> 5;
    int lane = threadIdx.x & 31;
    if (n >= N_NODES) return;

    float dv = g_dinv[n];
    float sl = dv * dv;
    float4 acc = ((const float4*)(h + (size_t)n * DH))[lane];
    acc.x *= sl; acc.y *= sl; acc.z *= sl; acc.w *= sl;

    int beg = g_row[n];
    int cnt = g_cnt[n];
    int e = beg;
    for (; e + 1 < beg + cnt; e += 2) {
        int s0 = g_csr_src[e];
        int s1 = g_csr_src[e + 1];
        float w0 = g_csr_w[e];
        float w1 = g_csr_w[e + 1];
        float4 v0 = ((const float4*)(h + (size_t)s0 * DH))[lane];
        float4 v1 = ((const float4*)(h + (size_t)s1 * DH))[lane];
        acc.x = fmaf(w0, v0.x, acc.x); acc.y = fmaf(w0, v0.y, acc.y);
        acc.z = fmaf(w0, v0.z, acc.z); acc.w = fmaf(w0, v0.w, acc.w);
        acc.x = fmaf(w1, v1.x, acc.x); acc.y = fmaf(w1, v1.y, acc.y);
        acc.z = fmaf(w1, v1.z, acc.z); acc.w = fmaf(w1, v1.w, acc.w);
    }
    if (e < beg + cnt) {
        int s0 = g_csr_src[e];
        float w0 = g_csr_w[e];
        float4 v0 = ((const float4*)(h + (size_t)s0 * DH))[lane];
        acc.x = fmaf(w0, v0.x, acc.x); acc.y = fmaf(w0, v0.y, acc.y);
        acc.z = fmaf(w0, v0.z, acc.z); acc.w = fmaf(w0, v0.w, acc.w);
    }
    if (APPLY) {
        float4 a  = ((const float4*)g_alpha1)[lane];
        float4 bt = ((const float4*)g_beta1)[lane];
        acc.x = fmaxf(fmaf(acc.x, a.x, bt.x), 0.f);
        acc.y = fmaxf(fmaf(acc.y, a.y, bt.y), 0.f);
        acc.z = fmaxf(fmaf(acc.z, a.z, bt.z), 0.f);
        acc.w = fmaxf(fmaf(acc.w, a.w, bt.w), 0.f);
    }
    ((float4*)(out + (size_t)n * DH))[lane] = acc;
}

// ---------------- final: relu(affine2(h)) @ Wfc + bfc, then log_softmax ----------------
__global__ __launch_bounds__(256) void k_fc_lsm(
    const float* __restrict__ h, const float* __restrict__ Wfc,
    const float* __restrict__ bfc, float* __restrict__ out)
{
    __shared__ float Ws[DH * DOUTC];
    __shared__ float bs[DOUTC];
    for (int i = threadIdx.x; i < DH * DOUTC; i += blockDim.x) Ws[i] = Wfc[i];
    if (threadIdx.x < DOUTC) bs[threadIdx.x] = bfc[threadIdx.x];
    __syncthreads();

    int row  = (blockIdx.x * blockDim.x + threadIdx.x) >> 5;
    int lane = threadIdx.x & 31;
    if (row >= N_NODES) return;

    const float* hr = h + (size_t)row * DH;
    float acc[DOUTC];
#pragma unroll
    for (int j = 0; j < DOUTC; j++) acc[j] = 0.0f;

#pragma unroll
    for (int i = 0; i < 4; i++) {
        int k = lane + i * 32;
        float hv = fmaxf(fmaf(hr[k], g_alpha2[k], g_beta2[k]), 0.f);
#pragma unroll
        for (int j = 0; j < DOUTC; j++)
            acc[j] = fmaf(hv, Ws[k * DOUTC + j], acc[j]);
    }
#pragma unroll
    for (int off = 16; off; off >>= 1)
#pragma unroll
        for (int j = 0; j < DOUTC; j++)
            acc[j] += __shfl_down_sync(0xffffffff, acc[j], off);

    if (lane == 0) {
        float m = -INFINITY;
#pragma unroll
        for (int j = 0; j < DOUTC; j++) { acc[j] += bs[j]; m = fmaxf(m, acc[j]); }
        float s = 0.0f;
#pragma unroll
        for (int j = 0; j < DOUTC; j++) s += expf(acc[j] - m);
        float lse = m + logf(s);
#pragma unroll
        for (int j = 0; j < DOUTC; j++)
            out[(size_t)row * DOUTC + j] = acc[j] - lse;
    }
}

// ---------------- launch ----------------
extern "C" void kernel_launch(void* const* d_in, const int* in_sizes, int n_in,
                              void* d_out, int out_size) {
    const float* x   = (const float*)d_in[0];
    const int*   ei  = (const int*)d_in[1];
    const float* W1  = (const float*)d_in[2];
    const float* b1  = (const float*)d_in[3];
    const float* g1  = (const float*)d_in[4];
    const float* be1 = (const float*)d_in[5];
    const float* rm1 = (const float*)d_in[6];
    const float* rv1 = (const float*)d_in[7];
    const float* W2  = (const float*)d_in[8];
    const float* b2  = (const float*)d_in[9];
    const float* g2  = (const float*)d_in[10];
    const float* be2 = (const float*)d_in[11];
    const float* rm2 = (const float*)d_in[12];
    const float* rv2 = (const float*)d_in[13];
    const float* Wfc = (const float*)d_in[14];
    const float* bfc = (const float*)d_in[15];
    float* out = (float*)d_out;

    float *p_h1, *p_h2, *p_h3;
    __nv_bfloat16 *p_B1H, *p_B1L, *p_B2H, *p_B2L;
    cudaGetSymbolAddress((void**)&p_h1, g_h1);
    cudaGetSymbolAddress((void**)&p_h2, g_h2);
    cudaGetSymbolAddress((void**)&p_h3, g_h3);
    cudaGetSymbolAddress((void**)&p_B1H, g_B1H);
    cudaGetSymbolAddress((void**)&p_B1L, g_B1L);
    cudaGetSymbolAddress((void**)&p_B2H, g_B2H);
    cudaGetSymbolAddress((void**)&p_B2L, g_B2L);

    static cudaStream_t s2 = nullptr;
    static cudaEvent_t evFork = nullptr, evJoin = nullptr;
    if (s2 == nullptr) {
        cudaStreamCreateWithFlags(&s2, cudaStreamNonBlocking);
        cudaEventCreateWithFlags(&evFork, cudaEventDisableTiming);
        cudaEventCreateWithFlags(&evJoin, cudaEventDisableTiming);
    }

    const int GEMM_BLOCKS = (N_NODES + 127) / 128;
    const int NODE_BLOCKS = (N_NODES + 255) / 256;
    const int EDGE_BLOCKS = (N_EDGES + 255) / 256;
    const int WARP_NODE_BLOCKS = (N_NODES + 7) / 8;

    // fork: CSR-build chain on s2 (independent of GEMM path)
    cudaEventRecord(evFork, 0);
    cudaStreamWaitEvent(s2, evFork, 0);

    k_prepB<DIN><<<(DH * DIN + 255) / 256, 256>>>(W1, p_B1H, p_B1L);     // 0 (main)
    k_zero<<<NODE_BLOCKS, 256, 0, s2>>>();                               // 1
    k_hist<<<EDGE_BLOCKS, 256, 0, s2>>>(ei);                             // 2
    gemm_cp<<<GEMM_BLOCKS, 256>>>(x, p_B1H, p_B1L, p_h1,
                                  N_NODES, DIN);                         // 3 (profiled)
    k_dinv<<<NODE_BLOCKS, 256, 0, s2>>>();                               // 4
    k_scan<<<1, SCAN_T, 0, s2>>>();                                      // 5
    k_fill<<<EDGE_BLOCKS, 256, 0, s2>>>(ei);                             // 6
    k_bnparam2<<<1, 256, 0, s2>>>(b1, g1, be1, rm1, rv1,
                                  b2, g2, be2, rm2, rv2);                // 7
    cudaEventRecord(evJoin, s2);
    cudaStreamWaitEvent(0, evJoin, 0);

    k_prepB<DH><<<(DH * DH + 255) / 256, 256>>>(W2, p_B2H, p_B2L);       // 8
    k_agg<1><<<WARP_NODE_BLOCKS, 256>>>(p_h1, p_h2);                     // 9
    gemm_cp<<<GEMM_BLOCKS, 256>>>(p_h2, p_B2H, p_B2L, p_h1,
                                  N_NODES, DH);                          // 10
    k_agg<0><<<WARP_NODE_BLOCKS, 256>>>(p_h1, p_h3);                     // 11
    k_fc_lsm<<<(N_NODES + 7) / 8, 256>>>(p_h3, Wfc, bfc, out);           // 12
}

// round 11
// speedup vs baseline: 1.4847x; 1.0593x over previous
#include <cuda_runtime.h>
#include <cuda_bf16.h>
#include <math.h>
#include <stdint.h>

#define N_NODES 50000
#define N_EDGES 800000
#define DIN 512
#define DH 128
#define DOUTC 7
#define BN_EPS 1e-5f
#define SCAN_T 1024

// ---------------- scratch (no cudaMalloc allowed) ----------------
__device__ int   g_cnt[N_NODES];
__device__ int   g_row[N_NODES];
__device__ int   g_cursor[N_NODES];
__device__ __align__(8) int2 g_csr[N_EDGES];   // .x = src, .y = weight bits
__device__ float g_dinv[N_NODES];
__device__ __align__(16) float g_h1[N_NODES * DH];
__device__ __align__(16) float g_h2[N_NODES * DH];
__device__ float g_alpha1[DH];
__device__ float g_beta1[DH];
__device__ float g_alpha2[DH];
__device__ float g_beta2[DH];
// pre-transposed + bf16-split weights: [n][k] K-major
__device__ __align__(16) __nv_bfloat16 g_B1H[DH * DIN];
__device__ __align__(16) __nv_bfloat16 g_B1L[DH * DIN];
__device__ __align__(16) __nv_bfloat16 g_B2H[DH * DH];
__device__ __align__(16) __nv_bfloat16 g_B2L[DH * DH];

// ---------------- CSR build ----------------
__global__ void k_zero() {
    int i = blockIdx.x * blockDim.x + threadIdx.x;
    if (i < N_NODES) g_cnt[i] = 0;
}

__global__ void k_hist(const int* __restrict__ ei) {
    int e = blockIdx.x * blockDim.x + threadIdx.x;
    if (e < N_EDGES) atomicAdd(&g_cnt[ei[N_EDGES + e]], 1);
}

__global__ void k_dinv() {
    int i = blockIdx.x * blockDim.x + threadIdx.x;
    if (i < N_NODES) g_dinv[i] = rsqrtf((float)(g_cnt[i] + 1));
}

__global__ __launch_bounds__(SCAN_T) void k_scan() {
    __shared__ int sums[SCAN_T];
    int t = threadIdx.x;
    const int CH = (N_NODES + SCAN_T - 1) / SCAN_T;
    int start = t * CH;
    int end = start + CH; if (end > N_NODES) end = N_NODES;
    int s = 0;
    for (int i = start; i < end; i++) s += g_cnt[i];
    sums[t] = s;
    __syncthreads();
    for (int off = 1; off < SCAN_T; off <<= 1) {
        int v = (t >= off) ? sums[t - off] : 0;
        __syncthreads();
        sums[t] += v;
        __syncthreads();
    }
    int run = (t == 0) ? 0 : sums[t - 1];
    for (int i = start; i < end; i++) {
        g_row[i] = run;
        g_cursor[i] = run;
        run += g_cnt[i];
    }
}

__global__ void k_fill(const int* __restrict__ ei) {
    int e = blockIdx.x * blockDim.x + threadIdx.x;
    if (e < N_EDGES) {
        int s = ei[e];
        int d = ei[N_EDGES + e];
        int p = atomicAdd(&g_cursor[d], 1);
        g_csr[p] = make_int2(s, __float_as_int(g_dinv[s] * g_dinv[d]));
    }
}

// ---------------- BN affines ----------------
__global__ void k_bnparam2(const float* __restrict__ b1, const float* __restrict__ g1,
                           const float* __restrict__ be1, const float* __restrict__ rm1,
                           const float* __restrict__ rv1,
                           const float* __restrict__ b2, const float* __restrict__ g2,
                           const float* __restrict__ be2, const float* __restrict__ rm2,
                           const float* __restrict__ rv2) {
    int c = threadIdx.x;
    if (c < DH) {
        float a = g1[c] * rsqrtf(rv1[c] + BN_EPS);
        g_alpha1[c] = a;
        g_beta1[c]  = (b1[c] - rm1[c]) * a + be1[c];
    } else {
        int d = c - DH;
        float a = g2[d] * rsqrtf(rv2[d] + BN_EPS);
        g_alpha2[d] = a;
        g_beta2[d]  = (b2[d] - rm2[d]) * a + be2[d];
    }
}

// ---------------- weight transpose + bf16 split ----------------
template<int K>
__global__ void k_prepB(const float* __restrict__ W,
                        __nv_bfloat16* __restrict__ BtH, __nv_bfloat16* __restrict__ BtL) {
    int idx = blockIdx.x * blockDim.x + threadIdx.x;
    if (idx < DH * K) {
        int n = idx / K, k = idx % K;
        float w = W[k * DH + n];
        __nv_bfloat16 h = __float2bfloat16(w);
        __nv_bfloat16 l = __float2bfloat16(w - __bfloat162float(h));
        BtH[idx] = h;
        BtL[idx] = l;
    }
}

// ---------------- bf16 MMA m16n8k16 ----------------
__device__ __forceinline__ void mma_bf16(float* d, const unsigned* a, const unsigned* b) {
    asm volatile(
        "mma.sync.aligned.m16n8k16.row.col.f32.bf16.bf16.f32 "
        "{%0,%1,%2,%3}, {%4,%5,%6,%7}, {%8,%9}, {%0,%1,%2,%3};"
        : "+f"(d[0]), "+f"(d[1]), "+f"(d[2]), "+f"(d[3])
        : "r"(a[0]), "r"(a[1]), "r"(a[2]), "r"(a[3]), "r"(b[0]), "r"(b[1]));
}

__device__ __forceinline__ void packsplit(float x, float y, unsigned& hi, unsigned& lo) {
    __nv_bfloat162 h = __floats2bfloat162_rn(x, y);
    hi = *(unsigned*)&h;
    float hx = __bfloat162float(__low2bfloat16(h));
    float hy = __bfloat162float(__high2bfloat16(h));
    __nv_bfloat162 l = __floats2bfloat162_rn(x - hx, y - hy);
    lo = *(unsigned*)&l;
}

__device__ __forceinline__ void cpa16(uint32_t dst, const void* src) {
    asm volatile("cp.async.cg.shared.global [%0], [%1], 16;" :: "r"(dst), "l"(src) : "memory");
}
__device__ __forceinline__ void cpa_commit() {
    asm volatile("cp.async.commit_group;" ::: "memory");
}

// ---------------- bf16x3 GEMM, cp.async double-buffered (proven R10) ----------------
#define ASTR 24
#define BSTR 12
__global__ __launch_bounds__(256, 2) void gemm_cp(
    const float* __restrict__ A,
    const __nv_bfloat16* __restrict__ BtH, const __nv_bfloat16* __restrict__ BtL,
    float* __restrict__ C, int M, int K)
{
    __shared__ float    Afp[2][128 * ASTR];
    __shared__ unsigned Bh[2][128 * BSTR];
    __shared__ unsigned Bl[2][128 * BSTR];

    int tid = threadIdx.x, wid = tid >> 5, lane = tid & 31;
    int wm = wid >> 1, wn = wid & 1;
    int g = lane >> 2, t4 = lane & 3;
    int m0 = blockIdx.x * 128;

    uint32_t aBase  = (uint32_t)__cvta_generic_to_shared(&Afp[0][0]);
    uint32_t bhBase = (uint32_t)__cvta_generic_to_shared(&Bh[0][0]);
    uint32_t blBase = (uint32_t)__cvta_generic_to_shared(&Bl[0][0]);

    int rA = tid >> 2, cA = tid & 3;
    int rA2 = (tid + 256) >> 2, cA2 = (tid + 256) & 3;
    int rowA  = m0 + rA;  if (rowA  >= M) rowA  = M - 1;
    int rowA2 = m0 + rA2; if (rowA2 >= M) rowA2 = M - 1;
    int nB = tid >> 1, qB = tid & 1;

    auto issue = [&](int t, int st) {
        int k0 = t * 16;
        cpa16(aBase + (uint32_t)(st * 128 * ASTR + rA * ASTR + cA * 4) * 4,
              A + (size_t)rowA * K + k0 + cA * 4);
        cpa16(aBase + (uint32_t)(st * 128 * ASTR + rA2 * ASTR + cA2 * 4) * 4,
              A + (size_t)rowA2 * K + k0 + cA2 * 4);
        cpa16(bhBase + (uint32_t)(st * 128 * BSTR + nB * BSTR + qB * 4) * 4,
              BtH + (size_t)nB * K + k0 + qB * 8);
        cpa16(blBase + (uint32_t)(st * 128 * BSTR + nB * BSTR + qB * 4) * 4,
              BtL + (size_t)nB * K + k0 + qB * 8);
        cpa_commit();
    };

    float acc[2][8][4];
#pragma unroll
    for (int mt = 0; mt < 2; mt++)
#pragma unroll
        for (int nt = 0; nt < 8; nt++)
#pragma unroll
            for (int j = 0; j < 4; j++) acc[mt][nt][j] = 0.0f;

    int T = K / 16;
    issue(0, 0);

    for (int t = 0; t < T; t++) {
        int cur = t & 1;
        if (t + 1 < T) {
            issue(t + 1, cur ^ 1);
            asm volatile("cp.async.wait_group 1;" ::: "memory");
        } else {
            asm volatile("cp.async.wait_group 0;" ::: "memory");
        }
        __syncthreads();

        const float* Ab = &Afp[cur][0];
        const unsigned* Bhb = &Bh[cur][0];
        const unsigned* Blb = &Bl[cur][0];

        unsigned ah[2][4], al[2][4];
#pragma unroll
        for (int mt = 0; mt < 2; mt++) {
            int mb = wm * 32 + mt * 16;
            float2 p0 = *(const float2*)&Ab[(mb + g)     * ASTR + 2 * t4];
            float2 p1 = *(const float2*)&Ab[(mb + 8 + g) * ASTR + 2 * t4];
            float2 p2 = *(const float2*)&Ab[(mb + g)     * ASTR + 8 + 2 * t4];
            float2 p3 = *(const float2*)&Ab[(mb + 8 + g) * ASTR + 8 + 2 * t4];
            packsplit(p0.x, p0.y, ah[mt][0], al[mt][0]);
            packsplit(p1.x, p1.y, ah[mt][1], al[mt][1]);
            packsplit(p2.x, p2.y, ah[mt][2], al[mt][2]);
            packsplit(p3.x, p3.y, ah[mt][3], al[mt][3]);
        }
        unsigned bh[8][2];
#pragma unroll
        for (int nt = 0; nt < 8; nt++) {
            int n = wn * 64 + nt * 8 + g;
            bh[nt][0] = Bhb[n * BSTR + t4];
            bh[nt][1] = Bhb[n * BSTR + 4 + t4];
        }
#pragma unroll
        for (int nt = 0; nt < 8; nt++)
#pragma unroll
            for (int mt = 0; mt < 2; mt++) mma_bf16(acc[mt][nt], ah[mt], bh[nt]);
#pragma unroll
        for (int nt = 0; nt < 8; nt++)
#pragma unroll
            for (int mt = 0; mt < 2; mt++) mma_bf16(acc[mt][nt], al[mt], bh[nt]);
#pragma unroll
        for (int nt = 0; nt < 8; nt++) {
            unsigned bl[2];
            int n = wn * 64 + nt * 8 + g;
            bl[0] = Blb[n * BSTR + t4];
            bl[1] = Blb[n * BSTR + 4 + t4];
#pragma unroll
            for (int mt = 0; mt < 2; mt++) mma_bf16(acc[mt][nt], ah[mt], bl);
        }
        __syncthreads();
    }

#pragma unroll
    for (int mt = 0; mt < 2; mt++) {
        int row0 = m0 + wm * 32 + mt * 16 + g;
        int row1 = row0 + 8;
#pragma unroll
        for (int nt = 0; nt < 8; nt++) {
            int col = wn * 64 + nt * 8 + 2 * t4;
            if (row0 < M)
                *(float2*)(C + (size_t)row0 * 128 + col) = make_float2(acc[mt][nt][0], acc[mt][nt][1]);
            if (row1 < M)
                *(float2*)(C + (size_t)row1 * 128 + col) = make_float2(acc[mt][nt][2], acc[mt][nt][3]);
        }
    }
}

// ---------------- gather core: warp accumulates weighted neighbor rows ----------------
__device__ __forceinline__ float4 agg_gather(const float* __restrict__ h, int n, int lane) {
    float dv = g_dinv[n];
    float sl = dv * dv;
    float4 acc = ((const float4*)(h + (size_t)n * DH))[lane];
    acc.x *= sl; acc.y *= sl; acc.z *= sl; acc.w *= sl;

    int e = g_row[n];
    int end = e + g_cnt[n];
    for (; e + 4 <= end; e += 4) {
        int2 c0 = g_csr[e],     c1 = g_csr[e + 1];
        int2 c2 = g_csr[e + 2], c3 = g_csr[e + 3];
        float4 v0 = ((const float4*)(h + (size_t)c0.x * DH))[lane];
        float4 v1 = ((const float4*)(h + (size_t)c1.x * DH))[lane];
        float4 v2 = ((const float4*)(h + (size_t)c2.x * DH))[lane];
        float4 v3 = ((const float4*)(h + (size_t)c3.x * DH))[lane];
        float w0 = __int_as_float(c0.y), w1 = __int_as_float(c1.y);
        float w2 = __int_as_float(c2.y), w3 = __int_as_float(c3.y);
        acc.x = fmaf(w0, v0.x, acc.x); acc.y = fmaf(w0, v0.y, acc.y);
        acc.z = fmaf(w0, v0.z, acc.z); acc.w = fmaf(w0, v0.w, acc.w);
        acc.x = fmaf(w1, v1.x, acc.x); acc.y = fmaf(w1, v1.y, acc.y);
        acc.z = fmaf(w1, v1.z, acc.z); acc.w = fmaf(w1, v1.w, acc.w);
        acc.x = fmaf(w2, v2.x, acc.x); acc.y = fmaf(w2, v2.y, acc.y);
        acc.z = fmaf(w2, v2.z, acc.z); acc.w = fmaf(w2, v2.w, acc.w);
        acc.x = fmaf(w3, v3.x, acc.x); acc.y = fmaf(w3, v3.y, acc.y);
        acc.z = fmaf(w3, v3.z, acc.z); acc.w = fmaf(w3, v3.w, acc.w);
    }
    for (; e < end; e++) {
        int2 c0 = g_csr[e];
        float w0 = __int_as_float(c0.y);
        float4 v0 = ((const float4*)(h + (size_t)c0.x * DH))[lane];
        acc.x = fmaf(w0, v0.x, acc.x); acc.y = fmaf(w0, v0.y, acc.y);
        acc.z = fmaf(w0, v0.z, acc.z); acc.w = fmaf(w0, v0.w, acc.w);
    }
    return acc;
}

// ---------------- layer-1 aggregation + affine1 + relu ----------------
__global__ __launch_bounds__(256) void k_agg1(
    const float* __restrict__ h, float* __restrict__ out)
{
    int n = (blockIdx.x * blockDim.x + threadIdx.x) >> 5;
    int lane = threadIdx.x & 31;
    if (n >= N_NODES) return;

    float4 acc = agg_gather(h, n, lane);
    float4 a  = ((const float4*)g_alpha1)[lane];
    float4 bt = ((const float4*)g_beta1)[lane];
    acc.x = fmaxf(fmaf(acc.x, a.x, bt.x), 0.f);
    acc.y = fmaxf(fmaf(acc.y, a.y, bt.y), 0.f);
    acc.z = fmaxf(fmaf(acc.z, a.z, bt.z), 0.f);
    acc.w = fmaxf(fmaf(acc.w, a.w, bt.w), 0.f);
    ((float4*)(out + (size_t)n * DH))[lane] = acc;
}

// ---------------- fused: layer-2 aggregation + affine2 + relu + FC + log_softmax ----------------
__global__ __launch_bounds__(256) void k_agg_fc(
    const float* __restrict__ h, const float* __restrict__ Wfc,
    const float* __restrict__ bfc, float* __restrict__ out)
{
    __shared__ float Ws[DH * DOUTC];
    __shared__ float bs[DOUTC];
    for (int i = threadIdx.x; i < DH * DOUTC; i += blockDim.x) Ws[i] = Wfc[i];
    if (threadIdx.x < DOUTC) bs[threadIdx.x] = bfc[threadIdx.x];
    __syncthreads();

    int n = (blockIdx.x * blockDim.x + threadIdx.x) >> 5;
    int lane = threadIdx.x & 31;
    if (n >= N_NODES) return;

    float4 v = agg_gather(h, n, lane);
    float4 a  = ((const float4*)g_alpha2)[lane];
    float4 bt = ((const float4*)g_beta2)[lane];
    v.x = fmaxf(fmaf(v.x, a.x, bt.x), 0.f);
    v.y = fmaxf(fmaf(v.y, a.y, bt.y), 0.f);
    v.z = fmaxf(fmaf(v.z, a.z, bt.z), 0.f);
    v.w = fmaxf(fmaf(v.w, a.w, bt.w), 0.f);

    // channels of this lane: 4*lane .. 4*lane+3
    const float* w0 = &Ws[(4 * lane + 0) * DOUTC];
    const float* w1 = &Ws[(4 * lane + 1) * DOUTC];
    const float* w2 = &Ws[(4 * lane + 2) * DOUTC];
    const float* w3 = &Ws[(4 * lane + 3) * DOUTC];
    float o[DOUTC];
#pragma unroll
    for (int q = 0; q < DOUTC; q++)
        o[q] = fmaf(v.x, w0[q], fmaf(v.y, w1[q], fmaf(v.z, w2[q], v.w * w3[q])));

#pragma unroll
    for (int off = 16; off; off >>= 1)
#pragma unroll
        for (int q = 0; q < DOUTC; q++)
            o[q] += __shfl_down_sync(0xffffffff, o[q], off);

    if (lane == 0) {
        float m = -INFINITY;
#pragma unroll
        for (int q = 0; q < DOUTC; q++) { o[q] += bs[q]; m = fmaxf(m, o[q]); }
        float s = 0.0f;
#pragma unroll
        for (int q = 0; q < DOUTC; q++) s += expf(o[q] - m);
        float lse = m + logf(s);
#pragma unroll
        for (int q = 0; q < DOUTC; q++)
            out[(size_t)n * DOUTC + q] = o[q] - lse;
    }
}

// ---------------- launch ----------------
extern "C" void kernel_launch(void* const* d_in, const int* in_sizes, int n_in,
                              void* d_out, int out_size) {
    const float* x   = (const float*)d_in[0];
    const int*   ei  = (const int*)d_in[1];
    const float* W1  = (const float*)d_in[2];
    const float* b1  = (const float*)d_in[3];
    const float* g1  = (const float*)d_in[4];
    const float* be1 = (const float*)d_in[5];
    const float* rm1 = (const float*)d_in[6];
    const float* rv1 = (const float*)d_in[7];
    const float* W2  = (const float*)d_in[8];
    const float* b2  = (const float*)d_in[9];
    const float* g2  = (const float*)d_in[10];
    const float* be2 = (const float*)d_in[11];
    const float* rm2 = (const float*)d_in[12];
    const float* rv2 = (const float*)d_in[13];
    const float* Wfc = (const float*)d_in[14];
    const float* bfc = (const float*)d_in[15];
    float* out = (float*)d_out;

    float *p_h1, *p_h2;
    __nv_bfloat16 *p_B1H, *p_B1L, *p_B2H, *p_B2L;
    cudaGetSymbolAddress((void**)&p_h1, g_h1);
    cudaGetSymbolAddress((void**)&p_h2, g_h2);
    cudaGetSymbolAddress((void**)&p_B1H, g_B1H);
    cudaGetSymbolAddress((void**)&p_B1L, g_B1L);
    cudaGetSymbolAddress((void**)&p_B2H, g_B2H);
    cudaGetSymbolAddress((void**)&p_B2L, g_B2L);

    static cudaStream_t s2 = nullptr;
    static cudaEvent_t evFork = nullptr, evJoin = nullptr;
    if (s2 == nullptr) {
        cudaStreamCreateWithFlags(&s2, cudaStreamNonBlocking);
        cudaEventCreateWithFlags(&evFork, cudaEventDisableTiming);
        cudaEventCreateWithFlags(&evJoin, cudaEventDisableTiming);
    }

    const int GEMM_BLOCKS = (N_NODES + 127) / 128;
    const int NODE_BLOCKS = (N_NODES + 255) / 256;
    const int EDGE_BLOCKS = (N_EDGES + 255) / 256;
    const int WARP_NODE_BLOCKS = (N_NODES + 7) / 8;

    // fork: CSR-build chain + weight prep on s2 (independent of GEMM1)
    cudaEventRecord(evFork, 0);
    cudaStreamWaitEvent(s2, evFork, 0);

    k_prepB<DIN><<<(DH * DIN + 255) / 256, 256>>>(W1, p_B1H, p_B1L);     // 0 (main)
    k_zero<<<NODE_BLOCKS, 256, 0, s2>>>();                               // 1
    k_hist<<<EDGE_BLOCKS, 256, 0, s2>>>(ei);                             // 2
    gemm_cp<<<GEMM_BLOCKS, 256>>>(x, p_B1H, p_B1L, p_h1,
                                  N_NODES, DIN);                         // 3 (profiled)
    k_dinv<<<NODE_BLOCKS, 256, 0, s2>>>();                               // 4
    k_scan<<<1, SCAN_T, 0, s2>>>();                                      // 5
    k_fill<<<EDGE_BLOCKS, 256, 0, s2>>>(ei);                             // 6
    k_bnparam2<<<1, 256, 0, s2>>>(b1, g1, be1, rm1, rv1,
                                  b2, g2, be2, rm2, rv2);                // 7
    k_prepB<DH><<<(DH * DH + 255) / 256, 256, 0, s2>>>(W2, p_B2H, p_B2L);// 8 (s2)
    cudaEventRecord(evJoin, s2);
    cudaStreamWaitEvent(0, evJoin, 0);

    k_agg1<<<WARP_NODE_BLOCKS, 256>>>(p_h1, p_h2);                       // 9
    gemm_cp<<<GEMM_BLOCKS, 256>>>(p_h2, p_B2H, p_B2L, p_h1,
                                  N_NODES, DH);                          // 10
    k_agg_fc<<<WARP_NODE_BLOCKS, 256>>>(p_h1, Wfc, bfc, out);            // 11
}